// round 5
// baseline (speedup 1.0000x reference)
#include <cuda_runtime.h>

#define B_ROWS 16384
#define D_DIM  1024
#define C_LAB  14
#define THREADS 256
#define NWARPS  8                            // THREADS/32
#define GRID    740                          // 148 SMs x 5 blocks/SM -> single wave
#define MAX_ROWS 23                          // ceil(16384/740)
#define ROW_STRIDE 196                       // 8 warps * 24 floats, padded to 16B-aligned stride

__device__ float        g_partials[GRID];
__device__ unsigned int g_count = 0;        // self-resetting; safe across graph replays

__device__ __forceinline__ float warp_sum(float v) {   // full 5-stage butterfly (cold paths only)
    #pragma unroll
    for (int o = 16; o > 0; o >>= 1) v += __shfl_down_sync(0xffffffffu, v, o);
    return v;
}

// ---------------------------------------------------------------------------
// Persistent-wave fused kernel. Hot loop does only a 2-stage partial warp
// reduction (6 SHFL + 3 STS per warp-row instead of 15 SHFL) to relieve the
// MIO pipe; the remaining 8-way sums are deferred to a one-time vectorized
// smem epilogue. Register carry keeps each row's HBM traffic to one read.
// ---------------------------------------------------------------------------
__global__ __launch_bounds__(THREADS, 5)
void rank_fused_kernel(const float4* __restrict__ zi,
                       const float4* __restrict__ zt,
                       const int*    __restrict__ labels,
                       float*        __restrict__ out) {
    // red[k][warp][quantity(3)][lane(8)] flattened, ROW_STRIDE-padded per row.
    __shared__ float red[(MAX_ROWS + 1) * ROW_STRIDE];   // ~18.8 KB
    __shared__ float wsum[NWARPS];
    __shared__ int   is_last;

    const int t    = threadIdx.x;
    const int lane = t & 31;
    const int warp = t >> 5;
    const int RW   = D_DIM / 4;                       // 256 float4 per row

    // balanced contiguous partition of rows across GRID blocks
    const int start = (int)(((long)blockIdx.x       * B_ROWS) / GRID);
    const int end   = (int)(((long)(blockIdx.x + 1) * B_ROWS) / GRID);
    const int nrows = end - start;                    // 22 or 23

    // prime the carry with the first row of this slice
    float4 ci = zi[(long)start * RW + t];
    float4 ct = zt[(long)start * RW + t];

    // ---- streaming phase: no barriers, minimal MIO work ----
    #pragma unroll 4
    for (int k = 0; k < nrows; k++) {
        const int nr = (start + k + 1) & (B_ROWS - 1);

        float4 ni = zi[(long)nr * RW + t];
        float4 nt = zt[(long)nr * RW + t];

        float p = ci.x * ct.x + ci.y * ct.y + ci.z * ct.z + ci.w * ct.w;  // paired
        float a = ni.x * ct.x + ni.y * ct.y + ni.z * ct.z + ni.w * ct.w;  // imp_img
        float b = nt.x * ci.x + nt.y * ci.y + nt.z * ci.z + nt.w * ci.w;  // imp_txt

        // 2-stage partial reduction: lanes 0..7 hold 8 partials per quantity
        p += __shfl_down_sync(0xffffffffu, p, 16);
        a += __shfl_down_sync(0xffffffffu, a, 16);
        b += __shfl_down_sync(0xffffffffu, b, 16);
        p += __shfl_down_sync(0xffffffffu, p, 8);
        a += __shfl_down_sync(0xffffffffu, a, 8);
        b += __shfl_down_sync(0xffffffffu, b, 8);

        if (lane < 8) {
            const int base = k * ROW_STRIDE + warp * 24 + lane;
            red[base]      = p;
            red[base + 8]  = a;
            red[base + 16] = b;
        }
        ci = ni;           // carry: next becomes current
        ct = nt;
    }

    __syncthreads();       // the ONLY barrier before the epilogue

    // ---- epilogue: threads 0..nrows-1 each finalize one row ----
    float acc = 0.0f;
    if (t < nrows) {
        const int r = start + t;
        const int j = (r + 1) & (B_ROWS - 1);

        // inline margin from labels (binary i32)
        const int* li = labels + (long)r * C_LAB;
        const int* lj = labels + (long)j * C_LAB;
        int n = 0, d = 0;
        bool eq = true;
        #pragma unroll
        for (int c = 0; c < C_LAB; c++) {
            int a = li[c], b = lj[c];
            eq = eq && (a == b);
            n += (a | b);
            d += (a ^ b);
        }
        float m;
        if (eq)         m = 0.0f;
        else if (n > 0) m = fmaxf(0.5f, (float)d / fmaxf((float)n, 1.0f));
        else            m = 0.5f;

        // sum the 8 warps x 8 lanes partials per quantity (vectorized LDS.128)
        float P = 0.0f, A = 0.0f, Bv = 0.0f;
        #pragma unroll
        for (int w = 0; w < NWARPS; w++) {
            const float4* q = (const float4*)&red[t * ROW_STRIDE + w * 24];
            float4 p0 = q[0], p1 = q[1];   // p partials (8)
            float4 a0 = q[2], a1 = q[3];   // a partials (8)
            float4 b0 = q[4], b1 = q[5];   // b partials (8)
            P  += (p0.x + p0.y + p0.z + p0.w) + (p1.x + p1.y + p1.z + p1.w);
            A  += (a0.x + a0.y + a0.z + a0.w) + (a1.x + a1.y + a1.z + a1.w);
            Bv += (b0.x + b0.y + b0.z + b0.w) + (b1.x + b1.y + b1.z + b1.w);
        }
        acc = fmaxf(A - P + m, 0.0f) + fmaxf(Bv - P + m, 0.0f);
    }

    // nrows <= 23 < 32 -> all row-accs live in warp 0
    if (warp == 0) {
        acc = warp_sum(acc);
        if (lane == 0) {
            g_partials[blockIdx.x] = acc;
            __threadfence();
            unsigned old = atomicAdd(&g_count, 1u);
            is_last = (old == GRID - 1) ? 1 : 0;
        }
    }
    __syncthreads();

    // ---- last block reduces all partials (fixed order -> deterministic) ----
    if (is_last) {
        float v = 0.0f;
        for (int i = t; i < GRID; i += THREADS)
            v += ((volatile float*)g_partials)[i];
        v = warp_sum(v);
        if (lane == 0) wsum[warp] = v;
        __syncthreads();
        if (warp == 0) {
            float x = (lane < NWARPS) ? wsum[lane] : 0.0f;
            #pragma unroll
            for (int o = 4; o > 0; o >>= 1)
                x += __shfl_down_sync(0xffffffffu, x, o);
            if (t == 0) {
                out[0]  = x * (1.0f / (float)B_ROWS);
                g_count = 0;                 // reset for next graph replay
            }
        }
    }
}

// ---------------------------------------------------------------------------
extern "C" void kernel_launch(void* const* d_in, const int* in_sizes, int n_in,
                              void* d_out, int out_size) {
    const float* zi     = (const float*)d_in[0];   // z_image [16384,1024] f32
    const float* zt     = (const float*)d_in[1];   // z_text  [16384,1024] f32
    const int*   labels = (const int*)d_in[2];     // labels  [16384,14]   i32

    rank_fused_kernel<<<GRID, THREADS>>>((const float4*)zi, (const float4*)zt,
                                         labels, (float*)d_out);
}